// round 16
// baseline (speedup 1.0000x reference)
#include <cuda_runtime.h>

#define LAMBDA_COORD 5.0f
#define LAMBDA_NO_OBJ 0.5f

#define NTHREADS 512
#define NBLOCKS  444    // 3 CTAs per SM, single wave (40 regs -> 61.4k/64k regs)

__global__ void zero_out_kernel(float* out) {
    out[0] = 0.0f;
    // PDL: signal completion early so the dependent main kernel can begin
    // launching during this kernel's epilogue.
    cudaTriggerProgrammaticLaunchCompletion();
}

__device__ __forceinline__ float warp_reduce(float v) {
    #pragma unroll
    for (int off = 16; off > 0; off >>= 1)
        v += __shfl_xor_sync(0xFFFFFFFFu, v, off);
    return v;
}

__global__ void __launch_bounds__(NTHREADS)
yolo_loss_kernel(
    const float*  __restrict__ main_boxes,   // [M,4]
    const float4* __restrict__ pred_boxes,   // [P]
    const float*  __restrict__ conf,         // [P]
    const float4* __restrict__ gmp,          // [NP4]
    const float4* __restrict__ gpp,          // [NP4]
    const int*    __restrict__ matched_main, // [P]
    const float*  __restrict__ matched_iou,  // [P]
    float* __restrict__ out,
    int P, int NP4, int chunk, int bchunk)
{
    const int b  = blockIdx.x;
    const int tx = threadIdx.x;

    const int pbase = b * chunk;
    const int pend  = min(pbase + chunk, NP4);
    const int bbase = b * bchunk;

    float acc = 0.0f;

    // ===== ONE independent front batch: 2 guarded prob rounds + box =====
    // chunk = 738 <= 2*NTHREADS, so two rounds cover it (round 2 partial).
    const int i0 = pbase + tx;
    const int i1 = i0 + NTHREADS;
    const bool v0 = i0 < pend;
    const bool v1 = i1 < pend;

    float4 a0, c0, a1, c1;
    if (v0) { a0 = gmp[i0]; c0 = gpp[i0]; }
    if (v1) { a1 = gmp[i1]; c1 = gpp[i1]; }

    const int  p       = bbase + tx;
    const bool has_box = (tx < bchunk) && (p < P);
    int   mm = 0;
    float cf = 0.0f, miou = 0.0f;
    float4 pb = make_float4(0.f, 0.f, 0.f, 0.f);
    if (has_box) {
        mm   = matched_main[p];
        cf   = conf[p];
        miou = matched_iou[p];
        pb   = pred_boxes[p];
    }

    // ===== compute =====
    float d;
    if (v0) {
        d = a0.x - c0.x; acc = fmaf(d, d, acc);
        d = a0.y - c0.y; acc = fmaf(d, d, acc);
        d = a0.z - c0.z; acc = fmaf(d, d, acc);
        d = a0.w - c0.w; acc = fmaf(d, d, acc);
    }
    if (v1) {
        d = a1.x - c1.x; acc = fmaf(d, d, acc);
        d = a1.y - c1.y; acc = fmaf(d, d, acc);
        d = a1.z - c1.z; acc = fmaf(d, d, acc);
        d = a1.w - c1.w; acc = fmaf(d, d, acc);
    }

    // generic spill loop (empty at this problem size; chunk <= 2*NTHREADS)
    for (int i = pbase + tx + 2 * NTHREADS; i < pend; i += NTHREADS) {
        float4 a = gmp[i];
        float4 c = gpp[i];
        d = a.x - c.x; acc = fmaf(d, d, acc);
        d = a.y - c.y; acc = fmaf(d, d, acc);
        d = a.z - c.z; acc = fmaf(d, d, acc);
        d = a.w - c.w; acc = fmaf(d, d, acc);
    }

    if (has_box) {
        if (mm >= 0) {
            const float* mbp = main_boxes + (size_t)mm * 4;  // hot 16KB table
            float mx = mbp[0], my = mbp[1], mw = mbp[2], mh = mbp[3];

            float dx = mx - pb.x;
            float dy = my - pb.y;
            float xy = dx * dx + dy * dy;

            float sw = sqrtf(fmaxf(mw, 0.0f)) - sqrtf(fmaxf(pb.z, 0.0f));
            float sh = sqrtf(fmaxf(mh, 0.0f)) - sqrtf(fmaxf(pb.w, 0.0f));
            float wh = sw * sw + sh * sh;

            float di = miou - cf;
            acc += LAMBDA_COORD * (xy + wh) + di * di;
        } else {
            acc += LAMBDA_NO_OBJ * cf * cf;
        }
    }

    // generic box spill loop (empty here: bchunk <= NTHREADS)
    for (int q = bbase + tx + NTHREADS; q < min(bbase + bchunk, P); q += NTHREADS) {
        int   m2  = matched_main[q];
        float c2f = conf[q];
        if (m2 >= 0) {
            float4 pq = pred_boxes[q];
            const float* mbp = main_boxes + (size_t)m2 * 4;
            float dx = mbp[0] - pq.x;
            float dy = mbp[1] - pq.y;
            float sw = sqrtf(fmaxf(mbp[2], 0.0f)) - sqrtf(fmaxf(pq.z, 0.0f));
            float sh = sqrtf(fmaxf(mbp[3], 0.0f)) - sqrtf(fmaxf(pq.w, 0.0f));
            float di = matched_iou[q] - c2f;
            acc += LAMBDA_COORD * (dx * dx + dy * dy + sw * sw + sh * sh) + di * di;
        } else {
            acc += LAMBDA_NO_OBJ * c2f * c2f;
        }
    }

    // ===== block reduction =====
    __shared__ float warp_sums[NTHREADS >> 5];
    float wsum = warp_reduce(acc);
    int lane = tx & 31;
    int wid  = tx >> 5;
    if (lane == 0) warp_sums[wid] = wsum;
    __syncthreads();

    if (wid == 0) {
        float v = (lane < (NTHREADS >> 5)) ? warp_sums[lane] : 0.0f;
        v = warp_reduce(v);
        if (lane == 0) {
            cudaGridDependencySynchronize();   // PDL: ensure zero kernel done
            atomicAdd(out, v);
        }
    }
}

extern "C" void kernel_launch(void* const* d_in, const int* in_sizes, int n_in,
                              void* d_out, int out_size) {
    const float*  main_boxes   = (const float*) d_in[0];
    const float4* pred_boxes   = (const float4*)d_in[1];
    const float*  conf         = (const float*) d_in[2];
    const float4* gmp          = (const float4*)d_in[3];
    const float4* gpp          = (const float4*)d_in[4];
    const int*    matched_main = (const int*)   d_in[5];
    const float*  matched_iou  = (const float*) d_in[6];
    float* out = (float*)d_out;

    int P   = in_sizes[2];      // 32768
    int NP4 = in_sizes[3] / 4;  // 327680

    int chunk  = (NP4 + NBLOCKS - 1) / NBLOCKS;  // 738
    int bchunk = (P   + NBLOCKS - 1) / NBLOCKS;  // 74

    zero_out_kernel<<<1, 1>>>(out);

    cudaLaunchConfig_t cfg = {};
    cfg.gridDim  = dim3(NBLOCKS, 1, 1);
    cfg.blockDim = dim3(NTHREADS, 1, 1);
    cfg.dynamicSmemBytes = 0;
    cfg.stream = 0;
    cudaLaunchAttribute attrs[1];
    attrs[0].id = cudaLaunchAttributeProgrammaticStreamSerialization;
    attrs[0].val.programmaticStreamSerializationAllowed = 1;
    cfg.attrs = attrs;
    cfg.numAttrs = 1;

    cudaLaunchKernelEx(&cfg, yolo_loss_kernel,
                       main_boxes, pred_boxes, conf, gmp, gpp,
                       matched_main, matched_iou, out, P, NP4, chunk, bchunk);
}

// round 17
// speedup vs baseline: 1.1055x; 1.1055x over previous
#include <cuda_runtime.h>

#define LAMBDA_COORD 5.0f
#define LAMBDA_NO_OBJ 0.5f

#define NTHREADS 512
#define NBLOCKS  296    // 2 CTAs per SM, single wave (empirical optimum)

__global__ void zero_out_kernel(float* out) {
    out[0] = 0.0f;
    // PDL: signal completion early so the dependent main kernel can begin
    // launching during this kernel's epilogue.
    cudaTriggerProgrammaticLaunchCompletion();
}

__device__ __forceinline__ float warp_reduce(float v) {
    #pragma unroll
    for (int off = 16; off > 0; off >>= 1)
        v += __shfl_xor_sync(0xFFFFFFFFu, v, off);
    return v;
}

__global__ void __launch_bounds__(NTHREADS)
yolo_loss_kernel(
    const float*  __restrict__ main_boxes,   // [M,4]
    const float4* __restrict__ pred_boxes,   // [P]
    const float*  __restrict__ conf,         // [P]
    const float4* __restrict__ gmp,          // [NP4]
    const float4* __restrict__ gpp,          // [NP4]
    const int*    __restrict__ matched_main, // [P]
    const float*  __restrict__ matched_iou,  // [P]
    float* __restrict__ out,
    int P, int NP4, int chunk, int bchunk)
{
    const int b  = blockIdx.x;
    const int tx = threadIdx.x;

    const int pbase = b * chunk;
    const int pend  = min(pbase + chunk, NP4);
    const int bbase = b * bchunk;

    float acc = 0.0f;

    // ===== ONE independent front batch (R12/R15-proven structure) =====
    const int i0 = pbase + tx;
    const int i1 = i0 + NTHREADS;
    const int i2 = i1 + NTHREADS;
    const bool v0 = i0 < pend;
    const bool v1 = i1 < pend;
    const bool v2 = i2 < pend;

    float4 a0, c0, a1, c1, a2, c2;
    if (v0) { a0 = gmp[i0]; c0 = gpp[i0]; }
    if (v1) { a1 = gmp[i1]; c1 = gpp[i1]; }
    if (v2) { a2 = gmp[i2]; c2 = gpp[i2]; }

    const int  p       = bbase + tx;
    const bool has_box = (tx < bchunk) && (p < P);   // warp-uniform (bchunk=112)
    int   mm = 0;
    float cf = 0.0f, miou = 0.0f;
    float4 pb = make_float4(0.f, 0.f, 0.f, 0.f);
    if (has_box) {
        mm   = matched_main[p];
        cf   = conf[p];
        miou = matched_iou[p];
        pb   = pred_boxes[p];
    }

    // ===== compute =====
    float d;
    if (v0) {
        d = a0.x - c0.x; acc = fmaf(d, d, acc);
        d = a0.y - c0.y; acc = fmaf(d, d, acc);
        d = a0.z - c0.z; acc = fmaf(d, d, acc);
        d = a0.w - c0.w; acc = fmaf(d, d, acc);
    }
    if (v1) {
        d = a1.x - c1.x; acc = fmaf(d, d, acc);
        d = a1.y - c1.y; acc = fmaf(d, d, acc);
        d = a1.z - c1.z; acc = fmaf(d, d, acc);
        d = a1.w - c1.w; acc = fmaf(d, d, acc);
    }
    if (v2) {
        d = a2.x - c2.x; acc = fmaf(d, d, acc);
        d = a2.y - c2.y; acc = fmaf(d, d, acc);
        d = a2.z - c2.z; acc = fmaf(d, d, acc);
        d = a2.w - c2.w; acc = fmaf(d, d, acc);
    }

    // generic spill loop (empty at this problem size; chunk <= 3*NTHREADS)
    for (int i = pbase + tx + 3 * NTHREADS; i < pend; i += NTHREADS) {
        float4 a = gmp[i];
        float4 c = gpp[i];
        d = a.x - c.x; acc = fmaf(d, d, acc);
        d = a.y - c.y; acc = fmaf(d, d, acc);
        d = a.z - c.z; acc = fmaf(d, d, acc);
        d = a.w - c.w; acc = fmaf(d, d, acc);
    }

    if (has_box) {
        if (mm >= 0) {
            const float* mbp = main_boxes + (size_t)mm * 4;  // hot 16KB table
            float mx = mbp[0], my = mbp[1], mw = mbp[2], mh = mbp[3];

            float dx = mx - pb.x;
            float dy = my - pb.y;
            float xy = dx * dx + dy * dy;

            float sw = sqrtf(fmaxf(mw, 0.0f)) - sqrtf(fmaxf(pb.z, 0.0f));
            float sh = sqrtf(fmaxf(mh, 0.0f)) - sqrtf(fmaxf(pb.w, 0.0f));
            float wh = sw * sw + sh * sh;

            float di = miou - cf;
            acc += LAMBDA_COORD * (xy + wh) + di * di;
        } else {
            acc += LAMBDA_NO_OBJ * cf * cf;
        }
    }

    // generic box spill loop (empty here: bchunk <= NTHREADS)
    for (int q = bbase + tx + NTHREADS; q < min(bbase + bchunk, P); q += NTHREADS) {
        int   m2  = matched_main[q];
        float c2f = conf[q];
        if (m2 >= 0) {
            float4 pq = pred_boxes[q];
            const float* mbp = main_boxes + (size_t)m2 * 4;
            float dx = mbp[0] - pq.x;
            float dy = mbp[1] - pq.y;
            float sw = sqrtf(fmaxf(mbp[2], 0.0f)) - sqrtf(fmaxf(pq.z, 0.0f));
            float sh = sqrtf(fmaxf(mbp[3], 0.0f)) - sqrtf(fmaxf(pq.w, 0.0f));
            float di = matched_iou[q] - c2f;
            acc += LAMBDA_COORD * (dx * dx + dy * dy + sw * sw + sh * sh) + di * di;
        } else {
            acc += LAMBDA_NO_OBJ * c2f * c2f;
        }
    }

    // ===== block reduction (padded warp_sums; 16-wide final tree) =====
    __shared__ float warp_sums[32];            // pad to 32, zero-filled once
    int lane = tx & 31;
    int wid  = tx >> 5;
    if (tx < 32) warp_sums[tx] = 0.0f;         // cheap, before the barrier
    float wsum = warp_reduce(acc);
    __syncthreads();                            // zero-fill visible
    if (lane == 0) warp_sums[wid] = wsum;
    __syncthreads();

    if (wid == 0) {
        float v = warp_sums[lane];             // unconditional (lanes 16-31: 0)
        #pragma unroll
        for (int off = 8; off > 0; off >>= 1)  // 16 values -> 4 shuffles
            v += __shfl_xor_sync(0xFFFFFFFFu, v, off);
        v += __shfl_xor_sync(0xFFFFFFFFu, v, 16);  // fold lanes 16-31 (zeros + symmetry)
        if (lane == 0) {
            cudaGridDependencySynchronize();   // PDL: ensure zero kernel done
            atomicAdd(out, v);
        }
    }
}

extern "C" void kernel_launch(void* const* d_in, const int* in_sizes, int n_in,
                              void* d_out, int out_size) {
    const float*  main_boxes   = (const float*) d_in[0];
    const float4* pred_boxes   = (const float4*)d_in[1];
    const float*  conf         = (const float*) d_in[2];
    const float4* gmp          = (const float4*)d_in[3];
    const float4* gpp          = (const float4*)d_in[4];
    const int*    matched_main = (const int*)   d_in[5];
    const float*  matched_iou  = (const float*) d_in[6];
    float* out = (float*)d_out;

    int P   = in_sizes[2];      // 32768
    int NP4 = in_sizes[3] / 4;  // 327680

    int chunk  = (NP4 + NBLOCKS - 1) / NBLOCKS;  // 1108
    int bchunk = (P   + NBLOCKS - 1) / NBLOCKS;  // 111
    bchunk     = (bchunk + 31) & ~31;            // 112: warp-uniform box predicate

    zero_out_kernel<<<1, 1>>>(out);

    cudaLaunchConfig_t cfg = {};
    cfg.gridDim  = dim3(NBLOCKS, 1, 1);
    cfg.blockDim = dim3(NTHREADS, 1, 1);
    cfg.dynamicSmemBytes = 0;
    cfg.stream = 0;
    cudaLaunchAttribute attrs[1];
    attrs[0].id = cudaLaunchAttributeProgrammaticStreamSerialization;
    attrs[0].val.programmaticStreamSerializationAllowed = 1;
    cfg.attrs = attrs;
    cfg.numAttrs = 1;

    cudaLaunchKernelEx(&cfg, yolo_loss_kernel,
                       main_boxes, pred_boxes, conf, gmp, gpp,
                       matched_main, matched_iou, out, P, NP4, chunk, bchunk);
}